// round 4
// baseline (speedup 1.0000x reference)
#include <cuda_runtime.h>

#define TM      16
#define NTH     256
#define DSTATE  256
#define DIN     512
#define NW      512
#define NSTEPS  60
#define NBLOCKS 128

typedef unsigned long long u64;

__constant__ float c_A[6][5] = {
    {0.f, 0.f, 0.f, 0.f, 0.f},
    {0.161f, 0.f, 0.f, 0.f, 0.f},
    {-0.008480655492356989f, 0.335480655492357f, 0.f, 0.f, 0.f},
    {2.8971530571054935f, -6.359448489975075f, 4.3622954328695815f, 0.f, 0.f},
    {5.325864828439257f, -11.748883564062828f, 7.4955393428898365f, -0.09249506636175525f, 0.f},
    {5.86145544294642f, -12.92096931784711f, 8.159367898576159f, -0.071584973281401f, -0.028269050394068383f}};
__constant__ float c_Bw[6] = {
    0.09646076681806523f, 0.01f, 0.4798896504144996f,
    1.379008574103742f, -3.290069515436081f, 2.324710524099774f};

__device__ float g_W1T[DIN * NW];
__device__ float g_W2T[NW * NW];
__device__ float g_W3T[NW * DSTATE];
__device__ float g_BU[NBLOCKS * NW * TM];   // per-CTA b1 + W1[:,256:]@u

// ---------------- packed f32x2 helpers ----------------
static __device__ __forceinline__ u64 pk2(float x, float y) {
    u64 d; asm("mov.b64 %0, {%1, %2};" : "=l"(d) : "f"(x), "f"(y)); return d;
}
static __device__ __forceinline__ u64 fma2(u64 a, u64 b, u64 c) {
    u64 d; asm("fma.rn.f32x2 %0, %1, %2, %3;" : "=l"(d) : "l"(a), "l"(b), "l"(c)); return d;
}

// ---------------- weight transpose: src[N][K] -> dst[K][N] ----------------
__global__ void transpose_kernel(int which, const float* __restrict__ src, int N, int K) {
    float* dst = (which == 0) ? g_W1T : (which == 1) ? g_W2T : g_W3T;
    __shared__ float tile[32][33];
    int kb = blockIdx.x * 32, nb = blockIdx.y * 32;
    int tx = threadIdx.x, ty = threadIdx.y;
    #pragma unroll
    for (int i = ty; i < 32; i += 8) tile[i][tx] = src[(nb + i) * K + (kb + tx)];
    __syncthreads();
    #pragma unroll
    for (int i = ty; i < 32; i += 8) dst[(kb + i) * N + (nb + tx)] = tile[tx][i];
}

// ---------------- 8m x 8n register-tile accumulate over KH k's ----------------
// Asm: SMEM k-major [k][16], pre-offset to (k0*TM + m0). Wg: global [k][ldw], pre-offset to (k0*ldw + n0).
static __device__ __forceinline__ void mma8x8(
    const float* __restrict__ Asm, const float* __restrict__ Wg,
    int ldw, int KH, u64* __restrict__ acc) {
    #pragma unroll 1
    for (int k = 0; k < KH; k += 2) {
        #pragma unroll
        for (int kk = 0; kk < 2; ++kk) {
            const float* wr = Wg + (size_t)(k + kk) * ldw;
            float4 w0 = *reinterpret_cast<const float4*>(wr);
            float4 w1 = *reinterpret_cast<const float4*>(wr + 4);
            const float* ar = Asm + (k + kk) * TM;
            ulonglong2 aa = *reinterpret_cast<const ulonglong2*>(ar);
            ulonglong2 ab = *reinterpret_cast<const ulonglong2*>(ar + 4);
            u64 ap0 = aa.x, ap1 = aa.y, ap2 = ab.x, ap3 = ab.y;
            float wv[8] = {w0.x, w0.y, w0.z, w0.w, w1.x, w1.y, w1.z, w1.w};
            #pragma unroll
            for (int nj = 0; nj < 8; ++nj) {
                u64 wd = pk2(wv[nj], wv[nj]);
                acc[nj * 4 + 0] = fma2(ap0, wd, acc[nj * 4 + 0]);
                acc[nj * 4 + 1] = fma2(ap1, wd, acc[nj * 4 + 1]);
                acc[nj * 4 + 2] = fma2(ap2, wd, acc[nj * 4 + 2]);
                acc[nj * 4 + 3] = fma2(ap3, wd, acc[nj * 4 + 3]);
            }
        }
    }
}

static __device__ __forceinline__ void store_partial(
    float* __restrict__ dst, int n0, int m0, const u64* __restrict__ acc) {
    #pragma unroll
    for (int nj = 0; nj < 8; ++nj) {
        ulonglong2 v, w;
        v.x = acc[nj * 4 + 0]; v.y = acc[nj * 4 + 1];
        w.x = acc[nj * 4 + 2]; w.y = acc[nj * 4 + 3];
        *reinterpret_cast<ulonglong2*>(dst + (n0 + nj) * TM + m0) = v;
        *reinterpret_cast<ulonglong2*>(dst + (n0 + nj) * TM + m0 + 4) = w;
    }
}

static __device__ __forceinline__ void zero_acc(u64* acc) {
    #pragma unroll
    for (int i = 0; i < 32; ++i) acc[i] = 0ull;
}

// ---------------- main fused Tsit5 kernel ----------------
__global__ void __launch_bounds__(NTH, 1)
ode_main(const float* __restrict__ x0, const float* __restrict__ uf,
         const float* __restrict__ b1, const float* __restrict__ b2,
         const float* __restrict__ b3, float* __restrict__ out) {
    extern __shared__ float smem[];
    float* A0 = smem;                 // [512][16]; z in rows 0-255; W2-out full
    float* A1 = A0 + NW * TM;         // [512][16]; W1-out
    float* P  = A1 + NW * TM;         // [512][16]; partial buffer
    float* Y  = P + NW * TM;          // [256][16]
    float* KB = Y + DSTATE * TM;      // [6][256][16]

    const int tid = threadIdx.x;
    const int r0 = blockIdx.x * TM;
    float* BUg = g_BU + (size_t)blockIdx.x * (NW * TM);

    // 512-wide gemm mapping: 2 k-halves x 128 positions (2 m-blocks x 64 n-blocks)
    const int half = tid >> 7;
    const int pos = tid & 127;
    const int m0 = (pos & 1) * 8;
    const int n0 = (pos >> 1) * 8;
    // 256-wide gemm mapping: 4 k-quarters x 64 positions
    const int q = tid >> 6;
    const int pos3 = tid & 63;
    const int m03 = (pos3 & 1) * 8;
    const int n03 = (pos3 >> 1) * 8;

    // init Y; load u into A0 rows 0-255 (k-major) for BU precompute
    for (int idx = tid; idx < TM * DSTATE; idx += NTH) {
        int m = idx >> 8, c = idx & 255;
        int r = r0 + m, traj = r & 1023;
        Y[c * TM + m] = x0[traj * DSTATE + c];
        A0[c * TM + m] = (r < 1024) ? uf[traj * DSTATE + c] : 0.f;
    }
    __syncthreads();

    // ---- BU = b1 + W1[:,256:512] @ u  (once; u constant over all stages) ----
    {
        u64 acc[32];
        zero_acc(acc);
        mma8x8(A0 + half * 128 * TM + m0,
               g_W1T + (size_t)(DSTATE + half * 128) * NW + n0, NW, 128, acc);
        store_partial(half ? P : A1, n0, m0, acc);
        __syncthreads();
        for (int i4 = tid; i4 < (NW * TM) / 4; i4 += NTH) {
            float4 a = reinterpret_cast<const float4*>(A1)[i4];
            float4 p = reinterpret_cast<const float4*>(P)[i4];
            float bb = b1[i4 >> 2];
            reinterpret_cast<float4*>(BUg)[i4] =
                make_float4(a.x + p.x + bb, a.y + p.y + bb, a.z + p.z + bb, a.w + p.w + bb);
        }
        __syncthreads();
    }

    const float H = 1.0f / 60.0f;

    #pragma unroll 1
    for (int step = 0; step < NSTEPS; ++step) {
        #pragma unroll 1
        for (int s = 0; s < 6; ++s) {
            // z = y + H * sum_j a_sj k_j  -> A0 rows [0,256)
            for (int i4 = tid; i4 < (DSTATE * TM) / 4; i4 += NTH) {
                float4 y = reinterpret_cast<const float4*>(Y)[i4];
                float4 a = make_float4(0.f, 0.f, 0.f, 0.f);
                for (int j = 0; j < s; ++j) {
                    float4 kv = reinterpret_cast<const float4*>(KB + j * DSTATE * TM)[i4];
                    float aj = c_A[s][j];
                    a.x += aj * kv.x; a.y += aj * kv.y;
                    a.z += aj * kv.z; a.w += aj * kv.w;
                }
                y.x += H * a.x; y.y += H * a.y; y.z += H * a.z; y.w += H * a.w;
                reinterpret_cast<float4*>(A0)[i4] = y;
            }
            __syncthreads();

            // gemm1: A1 = relu(BU + W1[:, :256] @ z), K=256, 2-way k-split
            {
                u64 acc[32];
                zero_acc(acc);
                mma8x8(A0 + half * 128 * TM + m0,
                       g_W1T + (size_t)(half * 128) * NW + n0, NW, 128, acc);
                store_partial(half ? P : A1, n0, m0, acc);
                __syncthreads();
                for (int i4 = tid; i4 < (NW * TM) / 4; i4 += NTH) {
                    float4 a = reinterpret_cast<const float4*>(A1)[i4];
                    float4 p = reinterpret_cast<const float4*>(P)[i4];
                    float4 bu = reinterpret_cast<const float4*>(BUg)[i4];
                    float4 v;
                    v.x = fmaxf(a.x + p.x + bu.x, 0.f);
                    v.y = fmaxf(a.y + p.y + bu.y, 0.f);
                    v.z = fmaxf(a.z + p.z + bu.z, 0.f);
                    v.w = fmaxf(a.w + p.w + bu.w, 0.f);
                    reinterpret_cast<float4*>(A1)[i4] = v;
                }
                __syncthreads();
            }
            // gemm2: A0 = relu(b2 + W2 @ A1), K=512, 2-way k-split
            {
                u64 acc[32];
                zero_acc(acc);
                mma8x8(A1 + half * 256 * TM + m0,
                       g_W2T + (size_t)(half * 256) * NW + n0, NW, 256, acc);
                store_partial(half ? P : A0, n0, m0, acc);
                __syncthreads();
                for (int i4 = tid; i4 < (NW * TM) / 4; i4 += NTH) {
                    float4 a = reinterpret_cast<const float4*>(A0)[i4];
                    float4 p = reinterpret_cast<const float4*>(P)[i4];
                    float bb = b2[i4 >> 2];
                    float4 v;
                    v.x = fmaxf(a.x + p.x + bb, 0.f);
                    v.y = fmaxf(a.y + p.y + bb, 0.f);
                    v.z = fmaxf(a.z + p.z + bb, 0.f);
                    v.w = fmaxf(a.w + p.w + bb, 0.f);
                    reinterpret_cast<float4*>(A0)[i4] = v;
                }
                __syncthreads();
            }
            // gemm3: k_s = b3 + W3 @ h2, K=512, N=256, 4-way k-split
            {
                float* KBs = KB + s * DSTATE * TM;
                u64 acc[32];
                zero_acc(acc);
                mma8x8(A0 + q * 128 * TM + m03,
                       g_W3T + (size_t)(q * 128) * DSTATE + n03, DSTATE, 128, acc);
                float* pdst = (q == 0) ? KBs : (q == 1) ? P : (q == 2) ? (P + DSTATE * TM) : A1;
                store_partial(pdst, n03, m03, acc);
                __syncthreads();
                for (int i4 = tid; i4 < (DSTATE * TM) / 4; i4 += NTH) {
                    float4 a  = reinterpret_cast<const float4*>(KBs)[i4];
                    float4 p1 = reinterpret_cast<const float4*>(P)[i4];
                    float4 p2 = reinterpret_cast<const float4*>(P + DSTATE * TM)[i4];
                    float4 p3 = reinterpret_cast<const float4*>(A1)[i4];
                    float bb = b3[i4 >> 2];
                    float4 v;
                    v.x = a.x + p1.x + p2.x + p3.x + bb;
                    v.y = a.y + p1.y + p2.y + p3.y + bb;
                    v.z = a.z + p1.z + p2.z + p3.z + bb;
                    v.w = a.w + p1.w + p2.w + p3.w + bb;
                    reinterpret_cast<float4*>(KBs)[i4] = v;
                }
                __syncthreads();
            }
        }
        // y += H * sum_i b_i k_i
        for (int i4 = tid; i4 < (DSTATE * TM) / 4; i4 += NTH) {
            float4 y = reinterpret_cast<const float4*>(Y)[i4];
            float4 a = make_float4(0.f, 0.f, 0.f, 0.f);
            #pragma unroll
            for (int j = 0; j < 6; ++j) {
                float4 kv = reinterpret_cast<const float4*>(KB + j * DSTATE * TM)[i4];
                float bj = c_Bw[j];
                a.x += bj * kv.x; a.y += bj * kv.y;
                a.z += bj * kv.z; a.w += bj * kv.w;
            }
            y.x += H * a.x; y.y += H * a.y; y.z += H * a.z; y.w += H * a.w;
            reinterpret_cast<float4*>(Y)[i4] = y;
        }
        __syncthreads();
    }

    for (int idx = tid; idx < TM * DSTATE; idx += NTH) {
        int m = idx >> 8, c = idx & 255;
        out[(size_t)(r0 + m) * DSTATE + c] = Y[c * TM + m];
    }
}

// ---------------- launch ----------------
extern "C" void kernel_launch(void* const* d_in, const int* in_sizes, int n_in,
                              void* d_out, int out_size) {
    (void)in_sizes; (void)n_in; (void)out_size;
    const float* x0 = (const float*)d_in[0];
    const float* uf = (const float*)d_in[1];
    const float* W1 = (const float*)d_in[2];
    const float* b1 = (const float*)d_in[3];
    const float* W2 = (const float*)d_in[4];
    const float* b2 = (const float*)d_in[5];
    const float* W3 = (const float*)d_in[6];
    const float* b3 = (const float*)d_in[7];
    float* out = (float*)d_out;

    dim3 tthreads(32, 8);
    transpose_kernel<<<dim3(DIN / 32, NW / 32), tthreads>>>(0, W1, NW, DIN);
    transpose_kernel<<<dim3(NW / 32, NW / 32), tthreads>>>(1, W2, NW, NW);
    transpose_kernel<<<dim3(NW / 32, DSTATE / 32), tthreads>>>(2, W3, DSTATE, NW);

    size_t smem_bytes = (size_t)(3 * NW * TM + 7 * DSTATE * TM) * sizeof(float);
    cudaFuncSetAttribute(ode_main, cudaFuncAttributeMaxDynamicSharedMemorySize, (int)smem_bytes);
    ode_main<<<NBLOCKS, NTH, smem_bytes>>>(x0, uf, b1, b2, b3, out);
}

// round 5
// speedup vs baseline: 1.8199x; 1.8199x over previous
#include <cuda_runtime.h>

#define TM      16
#define NTH     256
#define DSTATE  256
#define DIN     512
#define NW      512
#define NSTEPS  60
#define NBLOCKS 128

typedef unsigned long long u64;

__constant__ float c_A[6][5] = {
    {0.f, 0.f, 0.f, 0.f, 0.f},
    {0.161f, 0.f, 0.f, 0.f, 0.f},
    {-0.008480655492356989f, 0.335480655492357f, 0.f, 0.f, 0.f},
    {2.8971530571054935f, -6.359448489975075f, 4.3622954328695815f, 0.f, 0.f},
    {5.325864828439257f, -11.748883564062828f, 7.4955393428898365f, -0.09249506636175525f, 0.f},
    {5.86145544294642f, -12.92096931784711f, 8.159367898576159f, -0.071584973281401f, -0.028269050394068383f}};
__constant__ float c_Bw[6] = {
    0.09646076681806523f, 0.01f, 0.4798896504144996f,
    1.379008574103742f, -3.290069515436081f, 2.324710524099774f};

// +2 rows of padding: the pipelined GEMM tail prefetch overreads 2 k-rows
// (values never consumed).
__device__ float g_W1T[(DIN + 2) * NW];
__device__ float g_W2T[(NW + 2) * NW];
__device__ float g_W3T[(NW + 2) * DSTATE];
__device__ float g_BU[NBLOCKS * NW * TM];   // per-CTA b1 + W1[:,256:]@u

// ---------------- packed f32x2 helpers ----------------
static __device__ __forceinline__ u64 pk2(float x, float y) {
    u64 d; asm("mov.b64 %0, {%1, %2};" : "=l"(d) : "f"(x), "f"(y)); return d;
}
static __device__ __forceinline__ u64 fma2(u64 a, u64 b, u64 c) {
    u64 d; asm("fma.rn.f32x2 %0, %1, %2, %3;" : "=l"(d) : "l"(a), "l"(b), "l"(c)); return d;
}

// ---------------- weight transpose: src[N][K] -> dst[K][N] ----------------
__global__ void transpose_kernel(int which, const float* __restrict__ src, int N, int K) {
    float* dst = (which == 0) ? g_W1T : (which == 1) ? g_W2T : g_W3T;
    __shared__ float tile[32][33];
    int kb = blockIdx.x * 32, nb = blockIdx.y * 32;
    int tx = threadIdx.x, ty = threadIdx.y;
    #pragma unroll
    for (int i = ty; i < 32; i += 8) tile[i][tx] = src[(nb + i) * K + (kb + tx)];
    __syncthreads();
    #pragma unroll
    for (int i = ty; i < 32; i += 8) dst[(kb + i) * N + (nb + tx)] = tile[tx][i];
}

// ---------------- 8m x 8n pipelined register-tile GEMM ----------------
struct KB8 { float4 w0, w1; ulonglong2 a0, a1; };

static __device__ __forceinline__ KB8 ldk(const float* __restrict__ Asm,
                                          const float* __restrict__ Wg,
                                          int ldw, int k) {
    KB8 b;
    const float* wr = Wg + (size_t)k * ldw;
    b.w0 = *reinterpret_cast<const float4*>(wr);
    b.w1 = *reinterpret_cast<const float4*>(wr + 4);
    const float* ar = Asm + k * TM;
    b.a0 = *reinterpret_cast<const ulonglong2*>(ar);
    b.a1 = *reinterpret_cast<const ulonglong2*>(ar + 4);
    return b;
}

static __device__ __forceinline__ void cmp8(const KB8& b, u64* __restrict__ acc) {
    float wv[8] = {b.w0.x, b.w0.y, b.w0.z, b.w0.w, b.w1.x, b.w1.y, b.w1.z, b.w1.w};
    u64 ap0 = b.a0.x, ap1 = b.a0.y, ap2 = b.a1.x, ap3 = b.a1.y;
    #pragma unroll
    for (int nj = 0; nj < 8; ++nj) {
        u64 wd = pk2(wv[nj], wv[nj]);
        acc[nj * 4 + 0] = fma2(ap0, wd, acc[nj * 4 + 0]);
        acc[nj * 4 + 1] = fma2(ap1, wd, acc[nj * 4 + 1]);
        acc[nj * 4 + 2] = fma2(ap2, wd, acc[nj * 4 + 2]);
        acc[nj * 4 + 3] = fma2(ap3, wd, acc[nj * 4 + 3]);
    }
}

// KH must be a multiple of 4. Tail prefetch overreads 2 rows past KH in both
// Asm (lands in the adjacent SMEM buffer) and Wg (padded device arrays).
static __device__ __forceinline__ void mma8x8(
    const float* __restrict__ Asm, const float* __restrict__ Wg,
    int ldw, int KH, u64* __restrict__ acc) {
    KB8 b0 = ldk(Asm, Wg, ldw, 0);
    KB8 b1 = ldk(Asm, Wg, ldw, 1);
    #pragma unroll 1
    for (int k = 0; k < KH; k += 4) {
        KB8 c0 = ldk(Asm, Wg, ldw, k + 2);
        KB8 c1 = ldk(Asm, Wg, ldw, k + 3);
        cmp8(b0, acc);
        cmp8(b1, acc);
        b0 = ldk(Asm, Wg, ldw, k + 4);   // overread on last iter: discarded
        b1 = ldk(Asm, Wg, ldw, k + 5);
        cmp8(c0, acc);
        cmp8(c1, acc);
    }
}

static __device__ __forceinline__ void store_partial(
    float* __restrict__ dst, int n0, int m0, const u64* __restrict__ acc) {
    #pragma unroll
    for (int nj = 0; nj < 8; ++nj) {
        ulonglong2 v, w;
        v.x = acc[nj * 4 + 0]; v.y = acc[nj * 4 + 1];
        w.x = acc[nj * 4 + 2]; w.y = acc[nj * 4 + 3];
        *reinterpret_cast<ulonglong2*>(dst + (n0 + nj) * TM + m0) = v;
        *reinterpret_cast<ulonglong2*>(dst + (n0 + nj) * TM + m0 + 4) = w;
    }
}

static __device__ __forceinline__ void zero_acc(u64* acc) {
    #pragma unroll
    for (int i = 0; i < 32; ++i) acc[i] = 0ull;
}

// ---------------- main fused Tsit5 kernel ----------------
__global__ void __launch_bounds__(NTH, 1)
ode_main(const float* __restrict__ x0, const float* __restrict__ uf,
         const float* __restrict__ b1, const float* __restrict__ b2,
         const float* __restrict__ b3, float* __restrict__ out) {
    extern __shared__ float smem[];
    float* A0 = smem;                 // [512][16]
    float* A1 = A0 + NW * TM;         // [512][16]
    float* P  = A1 + NW * TM;         // [512][16]
    float* Y  = P + NW * TM;          // [256][16]
    float* KB = Y + DSTATE * TM;      // [6][256][16]

    const int tid = threadIdx.x;
    const int r0 = blockIdx.x * TM;
    float* BUg = g_BU + (size_t)blockIdx.x * (NW * TM);

    // 512-wide gemm mapping: 2 k-halves x (2 m-blocks x 64 n-blocks)
    const int half = tid >> 7;
    const int pos = tid & 127;
    const int m0 = (pos & 1) * 8;
    const int n0 = (pos >> 1) * 8;
    // 256-wide gemm mapping: 4 k-quarters x 64 positions
    const int q = tid >> 6;
    const int pos3 = tid & 63;
    const int m03 = (pos3 & 1) * 8;
    const int n03 = (pos3 >> 1) * 8;

    // init Y; u into A0 rows 0-255 (k-major) for BU precompute
    for (int idx = tid; idx < TM * DSTATE; idx += NTH) {
        int m = idx >> 8, c = idx & 255;
        int r = r0 + m, traj = r & 1023;
        Y[c * TM + m] = x0[traj * DSTATE + c];
        A0[c * TM + m] = (r < 1024) ? uf[traj * DSTATE + c] : 0.f;
    }
    __syncthreads();

    // ---- BU = b1 + W1[:,256:512] @ u ----
    {
        u64 acc[32];
        zero_acc(acc);
        mma8x8(A0 + half * 128 * TM + m0,
               g_W1T + (size_t)(DSTATE + half * 128) * NW + n0, NW, 128, acc);
        store_partial(half ? P : A1, n0, m0, acc);
        __syncthreads();
        for (int i4 = tid; i4 < (NW * TM) / 4; i4 += NTH) {
            float4 a = reinterpret_cast<const float4*>(A1)[i4];
            float4 p = reinterpret_cast<const float4*>(P)[i4];
            float bb = b1[i4 >> 2];
            reinterpret_cast<float4*>(BUg)[i4] =
                make_float4(a.x + p.x + bb, a.y + p.y + bb, a.z + p.z + bb, a.w + p.w + bb);
        }
        __syncthreads();
    }

    const float H = 1.0f / 60.0f;

    #pragma unroll 1
    for (int step = 0; step < NSTEPS; ++step) {
        #pragma unroll 1
        for (int s = 0; s < 6; ++s) {
            // z = y + H * sum_j a_sj k_j  -> A0 rows [0,256)
            for (int i4 = tid; i4 < (DSTATE * TM) / 4; i4 += NTH) {
                float4 y = reinterpret_cast<const float4*>(Y)[i4];
                float4 a = make_float4(0.f, 0.f, 0.f, 0.f);
                for (int j = 0; j < s; ++j) {
                    float4 kv = reinterpret_cast<const float4*>(KB + j * DSTATE * TM)[i4];
                    float aj = c_A[s][j];
                    a.x += aj * kv.x; a.y += aj * kv.y;
                    a.z += aj * kv.z; a.w += aj * kv.w;
                }
                y.x += H * a.x; y.y += H * a.y; y.z += H * a.z; y.w += H * a.w;
                reinterpret_cast<float4*>(A0)[i4] = y;
            }
            __syncthreads();

            // gemm1: A1 = relu(BU + W1[:, :256] @ z), K=256, 2-way k-split
            {
                u64 acc[32];
                zero_acc(acc);
                mma8x8(A0 + half * 128 * TM + m0,
                       g_W1T + (size_t)(half * 128) * NW + n0, NW, 128, acc);
                store_partial(half ? P : A1, n0, m0, acc);
                __syncthreads();
                for (int i4 = tid; i4 < (NW * TM) / 4; i4 += NTH) {
                    float4 a = reinterpret_cast<const float4*>(A1)[i4];
                    float4 p = reinterpret_cast<const float4*>(P)[i4];
                    float4 bu = reinterpret_cast<const float4*>(BUg)[i4];
                    float4 v;
                    v.x = fmaxf(a.x + p.x + bu.x, 0.f);
                    v.y = fmaxf(a.y + p.y + bu.y, 0.f);
                    v.z = fmaxf(a.z + p.z + bu.z, 0.f);
                    v.w = fmaxf(a.w + p.w + bu.w, 0.f);
                    reinterpret_cast<float4*>(A1)[i4] = v;
                }
                __syncthreads();
            }
            // gemm2: A0 = relu(b2 + W2 @ A1), K=512, 2-way k-split
            {
                u64 acc[32];
                zero_acc(acc);
                mma8x8(A1 + half * 256 * TM + m0,
                       g_W2T + (size_t)(half * 256) * NW + n0, NW, 256, acc);
                store_partial(half ? P : A0, n0, m0, acc);
                __syncthreads();
                for (int i4 = tid; i4 < (NW * TM) / 4; i4 += NTH) {
                    float4 a = reinterpret_cast<const float4*>(A0)[i4];
                    float4 p = reinterpret_cast<const float4*>(P)[i4];
                    float bb = b2[i4 >> 2];
                    float4 v;
                    v.x = fmaxf(a.x + p.x + bb, 0.f);
                    v.y = fmaxf(a.y + p.y + bb, 0.f);
                    v.z = fmaxf(a.z + p.z + bb, 0.f);
                    v.w = fmaxf(a.w + p.w + bb, 0.f);
                    reinterpret_cast<float4*>(A0)[i4] = v;
                }
                __syncthreads();
            }
            // gemm3: k_s = b3 + W3 @ h2, K=512, N=256, 4-way k-split
            {
                float* KBs = KB + s * DSTATE * TM;
                u64 acc[32];
                zero_acc(acc);
                mma8x8(A0 + q * 128 * TM + m03,
                       g_W3T + (size_t)(q * 128) * DSTATE + n03, DSTATE, 128, acc);
                float* pdst = (q == 0) ? KBs : (q == 1) ? P : (q == 2) ? (P + DSTATE * TM) : A1;
                store_partial(pdst, n03, m03, acc);
                __syncthreads();
                for (int i4 = tid; i4 < (DSTATE * TM) / 4; i4 += NTH) {
                    float4 a  = reinterpret_cast<const float4*>(KBs)[i4];
                    float4 p1 = reinterpret_cast<const float4*>(P)[i4];
                    float4 p2 = reinterpret_cast<const float4*>(P + DSTATE * TM)[i4];
                    float4 p3 = reinterpret_cast<const float4*>(A1)[i4];
                    float bb = b3[i4 >> 2];
                    float4 v;
                    v.x = a.x + p1.x + p2.x + p3.x + bb;
                    v.y = a.y + p1.y + p2.y + p3.y + bb;
                    v.z = a.z + p1.z + p2.z + p3.z + bb;
                    v.w = a.w + p1.w + p2.w + p3.w + bb;
                    reinterpret_cast<float4*>(KBs)[i4] = v;
                }
                __syncthreads();
            }
        }
        // y += H * sum_i b_i k_i
        for (int i4 = tid; i4 < (DSTATE * TM) / 4; i4 += NTH) {
            float4 y = reinterpret_cast<const float4*>(Y)[i4];
            float4 a = make_float4(0.f, 0.f, 0.f, 0.f);
            #pragma unroll
            for (int j = 0; j < 6; ++j) {
                float4 kv = reinterpret_cast<const float4*>(KB + j * DSTATE * TM)[i4];
                float bj = c_Bw[j];
                a.x += bj * kv.x; a.y += bj * kv.y;
                a.z += bj * kv.z; a.w += bj * kv.w;
            }
            y.x += H * a.x; y.y += H * a.y; y.z += H * a.z; y.w += H * a.w;
            reinterpret_cast<float4*>(Y)[i4] = y;
        }
        __syncthreads();
    }

    for (int idx = tid; idx < TM * DSTATE; idx += NTH) {
        int m = idx >> 8, c = idx & 255;
        out[(size_t)(r0 + m) * DSTATE + c] = Y[c * TM + m];
    }
}

// ---------------- launch ----------------
extern "C" void kernel_launch(void* const* d_in, const int* in_sizes, int n_in,
                              void* d_out, int out_size) {
    (void)in_sizes; (void)n_in; (void)out_size;
    const float* x0 = (const float*)d_in[0];
    const float* uf = (const float*)d_in[1];
    const float* W1 = (const float*)d_in[2];
    const float* b1 = (const float*)d_in[3];
    const float* W2 = (const float*)d_in[4];
    const float* b2 = (const float*)d_in[5];
    const float* W3 = (const float*)d_in[6];
    const float* b3 = (const float*)d_in[7];
    float* out = (float*)d_out;

    dim3 tthreads(32, 8);
    transpose_kernel<<<dim3(DIN / 32, NW / 32), tthreads>>>(0, W1, NW, DIN);
    transpose_kernel<<<dim3(NW / 32, NW / 32), tthreads>>>(1, W2, NW, NW);
    transpose_kernel<<<dim3(NW / 32, DSTATE / 32), tthreads>>>(2, W3, DSTATE, NW);

    size_t smem_bytes = (size_t)(3 * NW * TM + 7 * DSTATE * TM) * sizeof(float);
    cudaFuncSetAttribute(ode_main, cudaFuncAttributeMaxDynamicSharedMemorySize, (int)smem_bytes);
    ode_main<<<NBLOCKS, NTH, smem_bytes>>>(x0, uf, b1, b2, b3, out);
}